// round 5
// baseline (speedup 1.0000x reference)
#include <cuda_runtime.h>
#include <cstddef>

#define NMAX 50000

// per-node accumulated edge features: agg[n][u*3+c]  (96 floats per node)
__device__ float g_agg[NMAX * 96];

__device__ __forceinline__ float silu_f(float v) {
    return v / (1.0f + __expf(-v));
}
__device__ __forceinline__ void fma4(float4& a, const float4 x, const float4 w) {
    a.x = fmaf(x.x, w.x, a.x);
    a.y = fmaf(x.y, w.y, a.y);
    a.z = fmaf(x.z, w.z, a.z);
    a.w = fmaf(x.w, w.w, a.w);
}
__device__ __forceinline__ float hsum4(const float4 a) {
    return (a.x + a.y) + (a.z + a.w);
}

// ---------------------------------------------------------------- zero agg
__global__ void zero_kernel(float4* __restrict__ p, int n4) {
    int i = blockIdx.x * blockDim.x + threadIdx.x;
    if (i < n4) p[i] = make_float4(0.f, 0.f, 0.f, 0.f);
}

// ---------------------------------------------------------------- edge MLP
// one thread per edge; weights + per-thread h1/h2 staging in dynamic smem.
__global__ __launch_bounds__(128) void edge_kernel(
    const float* __restrict__ edge_attr,
    const float* __restrict__ edge_weight,
    const int*   __restrict__ edge_index,
    const float* __restrict__ W1, const float* __restrict__ b1,
    const float* __restrict__ W2, const float* __restrict__ b2,
    const float* __restrict__ W3, const float* __restrict__ b3,
    float* __restrict__ agg, int E)
{
    extern __shared__ float sm[];
    float* sW1 = sm;                 // [32][32]  (m-major, k contiguous)
    float* sW2 = sW1 + 1024;         // [64][32]
    float* sW3 = sW2 + 2048;         // [96][64]
    float* sB  = sW3 + 6144;         // b1(32) b2(64) b3(96)
    float* h1s = sB + 192;           // [128][36]  pad-36 rows -> conflict-free
    float* h2s = h1s + 128 * 36;     // [128][68]

    const int tid = threadIdx.x;
    #pragma unroll 1
    for (int i = tid; i < 1024; i += 128) sW1[i] = W1[i];
    #pragma unroll 1
    for (int i = tid; i < 2048; i += 128) sW2[i] = W2[i];
    #pragma unroll 1
    for (int i = tid; i < 6144; i += 128) sW3[i] = W3[i];
    if (tid < 32)  sB[tid]      = b1[tid];
    if (tid < 64)  sB[32 + tid] = b2[tid];
    if (tid < 96)  sB[96 + tid] = b3[tid];
    __syncthreads();

    const int e = blockIdx.x * 128 + tid;
    if (e >= E) return;

    float* my1 = h1s + tid * 36;
    float* my2 = h2s + tid * 68;

    // edge_attr row -> registers
    float4 xv[8];
    const float4* ap = (const float4*)(edge_attr + (size_t)e * 32);
    #pragma unroll
    for (int i = 0; i < 8; i++) xv[i] = ap[i];

    // ---- layer 1: 32 -> 32 ----
    #pragma unroll 1
    for (int mg = 0; mg < 8; mg++) {
        const int m = mg * 4;
        const float4* w0 = (const float4*)(sW1 + (m + 0) * 32);
        const float4* w1 = (const float4*)(sW1 + (m + 1) * 32);
        const float4* w2 = (const float4*)(sW1 + (m + 2) * 32);
        const float4* w3 = (const float4*)(sW1 + (m + 3) * 32);
        float4 a0 = make_float4(0.f,0.f,0.f,0.f), a1 = a0, a2 = a0, a3 = a0;
        #pragma unroll
        for (int k = 0; k < 8; k++) {
            const float4 x = xv[k];
            fma4(a0, x, w0[k]); fma4(a1, x, w1[k]);
            fma4(a2, x, w2[k]); fma4(a3, x, w3[k]);
        }
        const float4 bb = *(const float4*)(sB + m);
        my1[m + 0] = silu_f(hsum4(a0) + bb.x);
        my1[m + 1] = silu_f(hsum4(a1) + bb.y);
        my1[m + 2] = silu_f(hsum4(a2) + bb.z);
        my1[m + 3] = silu_f(hsum4(a3) + bb.w);
    }

    // ---- layer 2: 32 -> 64 ----
    #pragma unroll 1
    for (int mg = 0; mg < 16; mg++) {
        const int m = mg * 4;
        const float4* w0 = (const float4*)(sW2 + (m + 0) * 32);
        const float4* w1 = (const float4*)(sW2 + (m + 1) * 32);
        const float4* w2 = (const float4*)(sW2 + (m + 2) * 32);
        const float4* w3 = (const float4*)(sW2 + (m + 3) * 32);
        const float4* xi = (const float4*)my1;
        float4 a0 = make_float4(0.f,0.f,0.f,0.f), a1 = a0, a2 = a0, a3 = a0;
        #pragma unroll
        for (int k = 0; k < 8; k++) {
            const float4 x = xi[k];
            fma4(a0, x, w0[k]); fma4(a1, x, w1[k]);
            fma4(a2, x, w2[k]); fma4(a3, x, w3[k]);
        }
        const float4 bb = *(const float4*)(sB + 32 + m);
        my2[m + 0] = silu_f(hsum4(a0) + bb.x);
        my2[m + 1] = silu_f(hsum4(a1) + bb.y);
        my2[m + 2] = silu_f(hsum4(a2) + bb.z);
        my2[m + 3] = silu_f(hsum4(a3) + bb.w);
    }

    // ---- layer 3: 64 -> 96, cutoff scale, vector-atomic accumulate ----
    const float wgt = edge_weight[e];
    const float cc  = (wgt < 5.0f)
                    ? (0.5f * (cosf(wgt * 0.62831853071795865f) + 1.0f))
                    : 0.0f;
    const int dst = edge_index[E + e];   // edge_index row 1
    float* ag = agg + (size_t)dst * 96;

    #pragma unroll 1
    for (int mg = 0; mg < 24; mg++) {
        const int m = mg * 4;
        const float4* w0 = (const float4*)(sW3 + (m + 0) * 64);
        const float4* w1 = (const float4*)(sW3 + (m + 1) * 64);
        const float4* w2 = (const float4*)(sW3 + (m + 2) * 64);
        const float4* w3 = (const float4*)(sW3 + (m + 3) * 64);
        const float4* xi = (const float4*)my2;
        float4 a0 = make_float4(0.f,0.f,0.f,0.f), a1 = a0, a2 = a0, a3 = a0;
        #pragma unroll
        for (int k = 0; k < 16; k++) {
            const float4 x = xi[k];
            fma4(a0, x, w0[k]); fma4(a1, x, w1[k]);
            fma4(a2, x, w2[k]); fma4(a3, x, w3[k]);
        }
        const float4 bb = *(const float4*)(sB + 96 + m);
        float4 r;
        r.x = silu_f(hsum4(a0) + bb.x) * cc;
        r.y = silu_f(hsum4(a1) + bb.y) * cc;
        r.z = silu_f(hsum4(a2) + bb.z) * cc;
        r.w = silu_f(hsum4(a3) + bb.w) * cc;
        atomicAdd((float4*)(ag + m), r);
    }
}

// --------------------------------------------------------------- node side
// warp per node, lane = unit. Components held per-lane, unit-mixing linears
// go through shared comps (broadcast reads) and shared Wt (stride-36 pad).
__device__ __forceinline__ void mix9(const float* __restrict__ wI,
                                     const float* __restrict__ wA,
                                     const float* __restrict__ wS,
                                     const float* __restrict__ cb,   // &cs[warp][0][0]
                                     float o[9])
{
    #pragma unroll
    for (int i = 0; i < 9; i++) o[i] = 0.f;
    #pragma unroll
    for (int k = 0; k < 8; k++) {
        const float4 vi = *(const float4*)(wI + 4 * k);
        const float4 va = *(const float4*)(wA + 4 * k);
        const float4 vs = *(const float4*)(wS + 4 * k);
        float4 c;
        c = *(const float4*)(cb + 0 * 32 + 4 * k);
        o[0] += vi.x*c.x + vi.y*c.y + vi.z*c.z + vi.w*c.w;
        c = *(const float4*)(cb + 1 * 32 + 4 * k);
        o[1] += va.x*c.x + va.y*c.y + va.z*c.z + va.w*c.w;
        c = *(const float4*)(cb + 2 * 32 + 4 * k);
        o[2] += va.x*c.x + va.y*c.y + va.z*c.z + va.w*c.w;
        c = *(const float4*)(cb + 3 * 32 + 4 * k);
        o[3] += va.x*c.x + va.y*c.y + va.z*c.z + va.w*c.w;
        c = *(const float4*)(cb + 4 * 32 + 4 * k);
        o[4] += vs.x*c.x + vs.y*c.y + vs.z*c.z + vs.w*c.w;
        c = *(const float4*)(cb + 5 * 32 + 4 * k);
        o[5] += vs.x*c.x + vs.y*c.y + vs.z*c.z + vs.w*c.w;
        c = *(const float4*)(cb + 6 * 32 + 4 * k);
        o[6] += vs.x*c.x + vs.y*c.y + vs.z*c.z + vs.w*c.w;
        c = *(const float4*)(cb + 7 * 32 + 4 * k);
        o[7] += vs.x*c.x + vs.y*c.y + vs.z*c.z + vs.w*c.w;
        c = *(const float4*)(cb + 8 * 32 + 4 * k);
        o[8] += vs.x*c.x + vs.y*c.y + vs.z*c.z + vs.w*c.w;
    }
}

__global__ __launch_bounds__(512) void node_kernel(
    const float* __restrict__ X,
    const float* __restrict__ Wt,
    const float* __restrict__ agg,
    float* __restrict__ out, int N)
{
    __shared__ __align__(16) float sWt[6 * 32 * 36];   // [t][m][k], k row padded to 36
    __shared__ __align__(16) float cs[16][9][32];      // per-warp component staging

    const int tid = threadIdx.x;
    #pragma unroll 1
    for (int i = tid; i < 6144; i += 512) {
        const int t = i >> 10, m = (i >> 5) & 31, k = i & 31;
        sWt[(t * 32 + m) * 36 + k] = Wt[i];
    }
    __syncthreads();

    const int warp = tid >> 5, lane = tid & 31;
    const int n = blockIdx.x * 16 + warp;
    if (n >= N) return;

    // load X[n,:,:,lane] (row-major i*3+j)
    const float* xp = X + (size_t)n * 288 + lane;
    float x[9];
    #pragma unroll
    for (int i = 0; i < 9; i++) x[i] = xp[i * 32];

    float nrm = 1.0f;
    #pragma unroll
    for (int i = 0; i < 9; i++) nrm += x[i] * x[i];
    const float inv = 1.0f / nrm;
    float xn[9];
    #pragma unroll
    for (int i = 0; i < 9; i++) xn[i] = x[i] * inv;

    // decompose Xn -> 9 independent comps {i0, a01,a02,a12, s00,s11,s01,s02,s12}
    const float tr3 = (xn[0] + xn[4] + xn[8]) * (1.0f / 3.0f);
    float c1[9];
    c1[0] = tr3;
    c1[1] = 0.5f * (xn[1] - xn[3]);
    c1[2] = 0.5f * (xn[2] - xn[6]);
    c1[3] = 0.5f * (xn[5] - xn[7]);
    c1[4] = xn[0] - tr3;
    c1[5] = xn[4] - tr3;
    c1[6] = 0.5f * (xn[1] + xn[3]);
    c1[7] = 0.5f * (xn[2] + xn[6]);
    c1[8] = 0.5f * (xn[5] + xn[7]);

    #pragma unroll
    for (int i = 0; i < 9; i++) cs[warp][i][lane] = c1[i];
    __syncwarp();

    float o[9];   // post-linear comps (Iy, Ay*, Sy*)
    mix9(sWt + (0 * 32 + lane) * 36,
         sWt + (1 * 32 + lane) * 36,
         sWt + (2 * 32 + lane) * 36,
         &cs[warp][0][0], o);

    // per-(node,unit) aggregated edge weights
    const float* ag = agg + (size_t)n * 96 + lane * 3;
    const float aI = ag[0], aA = ag[1], aS = ag[2];

    // full 3x3 Y and msg G per unit
    float Y[9], G[9];
    Y[0] = o[0] + o[4];  Y[1] = o[6] + o[1];  Y[2] = o[7] + o[2];
    Y[3] = o[6] - o[1];  Y[4] = o[0] + o[5];  Y[5] = o[8] + o[3];
    Y[6] = o[7] - o[2];  Y[7] = o[8] - o[3];  Y[8] = o[0] - o[4] - o[5];

    const float mI = o[0] * aI;
    const float mA1 = o[1] * aA, mA2 = o[2] * aA, mA3 = o[3] * aA;
    const float mS4 = o[4] * aS, mS5 = o[5] * aS;
    const float mS6 = o[6] * aS, mS7 = o[7] * aS, mS8 = o[8] * aS;
    G[0] = mI + mS4;   G[1] = mS6 + mA1;  G[2] = mS7 + mA2;
    G[3] = mS6 - mA1;  G[4] = mI + mS5;   G[5] = mS8 + mA3;
    G[6] = mS7 - mA2;  G[7] = mS8 - mA3;  G[8] = mI - mS4 - mS5;

    // M = Y*G + G*Y (3x3 per unit)
    float M[9];
    #pragma unroll
    for (int i = 0; i < 3; i++) {
        #pragma unroll
        for (int l = 0; l < 3; l++) {
            float s = 0.f;
            #pragma unroll
            for (int j = 0; j < 3; j++)
                s += Y[i*3+j] * G[j*3+l] + G[i*3+j] * Y[j*3+l];
            M[i*3+l] = s;
        }
    }

    float nrm2 = 1.0f;
    #pragma unroll
    for (int i = 0; i < 9; i++) nrm2 += M[i] * M[i];
    const float inv2 = 1.0f / nrm2;

    const float tm = (M[0] + M[4] + M[8]) * (1.0f / 3.0f);
    float c2[9];
    c2[0] = tm;
    c2[1] = 0.5f * (M[1] - M[3]);
    c2[2] = 0.5f * (M[2] - M[6]);
    c2[3] = 0.5f * (M[5] - M[7]);
    c2[4] = M[0] - tm;
    c2[5] = M[4] - tm;
    c2[6] = 0.5f * (M[1] + M[3]);
    c2[7] = 0.5f * (M[2] + M[6]);
    c2[8] = 0.5f * (M[5] + M[7]);
    #pragma unroll
    for (int i = 0; i < 9; i++) c2[i] *= inv2;

    __syncwarp();
    #pragma unroll
    for (int i = 0; i < 9; i++) cs[warp][i][lane] = c2[i];
    __syncwarp();

    float d[9];
    mix9(sWt + (3 * 32 + lane) * 36,
         sWt + (4 * 32 + lane) * 36,
         sWt + (5 * 32 + lane) * 36,
         &cs[warp][0][0], d);

    // dX full 3x3
    float D[9];
    D[0] = d[0] + d[4];  D[1] = d[6] + d[1];  D[2] = d[7] + d[2];
    D[3] = d[6] - d[1];  D[4] = d[0] + d[5];  D[5] = d[8] + d[3];
    D[6] = d[7] - d[2];  D[7] = d[8] - d[3];  D[8] = d[0] - d[4] - d[5];

    // out = Xn + dX + dX@dX
    float* op = out + (size_t)n * 288 + lane;
    #pragma unroll
    for (int i = 0; i < 3; i++) {
        #pragma unroll
        for (int l = 0; l < 3; l++) {
            float s = xn[i*3+l] + D[i*3+l];
            #pragma unroll
            for (int j = 0; j < 3; j++)
                s += D[i*3+j] * D[j*3+l];
            op[(i*3+l) * 32] = s;
        }
    }
}

// ------------------------------------------------------------------- launch
extern "C" void kernel_launch(void* const* d_in, const int* in_sizes, int n_in,
                              void* d_out, int out_size)
{
    const float* X  = (const float*)d_in[0];
    const int*   ei = (const int*)  d_in[1];
    const float* ew = (const float*)d_in[2];
    const float* ea = (const float*)d_in[3];
    const float* W1 = (const float*)d_in[4];
    const float* b1 = (const float*)d_in[5];
    const float* W2 = (const float*)d_in[6];
    const float* b2 = (const float*)d_in[7];
    const float* W3 = (const float*)d_in[8];
    const float* b3 = (const float*)d_in[9];
    const float* Wt = (const float*)d_in[10];
    float* out = (float*)d_out;

    const int N = in_sizes[0] / 288;   // X: (N,3,3,32)
    const int E = in_sizes[2];         // edge_weight: (E,)

    float* agg = nullptr;
    cudaGetSymbolAddress((void**)&agg, g_agg);

    // 1) zero per-node accumulator
    const int n4 = N * 24;             // N*96/4 float4s
    zero_kernel<<<(n4 + 255) / 256, 256>>>((float4*)agg, n4);

    // 2) edge MLP + atomic segment accumulation
    const int edge_smem = (1024 + 2048 + 6144 + 192 + 128 * 36 + 128 * 68) * 4; // 90880 B
    cudaFuncSetAttribute(edge_kernel, cudaFuncAttributeMaxDynamicSharedMemorySize, edge_smem);
    edge_kernel<<<(E + 127) / 128, 128, edge_smem>>>(
        ea, ew, ei, W1, b1, W2, b2, W3, b3, agg, E);

    // 3) node-local tensor update
    node_kernel<<<(N + 15) / 16, 512>>>(X, Wt, agg, out, N);
}

// round 6
// speedup vs baseline: 1.0037x; 1.0037x over previous
#include <cuda_runtime.h>
#include <cstddef>

#define NMAX 50000

// per-node accumulated edge features: agg[n][u*3+c]  (96 floats per node)
__device__ float g_agg[NMAX * 96];

__device__ __forceinline__ float silu_f(float v) {
    return v / (1.0f + __expf(-v));
}
__device__ __forceinline__ void fma4(float4& a, const float4 x, const float4 w) {
    a.x = fmaf(x.x, w.x, a.x);
    a.y = fmaf(x.y, w.y, a.y);
    a.z = fmaf(x.z, w.z, a.z);
    a.w = fmaf(x.w, w.w, a.w);
}
__device__ __forceinline__ float hsum4(const float4 a) {
    return (a.x + a.y) + (a.z + a.w);
}

// ---------------------------------------------------------------- zero agg
__global__ void zero_kernel(float4* __restrict__ p, int n4) {
    int i = blockIdx.x * blockDim.x + threadIdx.x;
    if (i < n4) p[i] = make_float4(0.f, 0.f, 0.f, 0.f);
}

// ---------------------------------------------------------------- edge MLP
// one thread per edge; weights + per-thread h1/h2 staging in dynamic smem.
__global__ __launch_bounds__(128) void edge_kernel(
    const float* __restrict__ edge_attr,
    const float* __restrict__ edge_weight,
    const int*   __restrict__ edge_index,
    const float* __restrict__ W1, const float* __restrict__ b1,
    const float* __restrict__ W2, const float* __restrict__ b2,
    const float* __restrict__ W3, const float* __restrict__ b3,
    float* __restrict__ agg, int E)
{
    extern __shared__ float sm[];
    float* sW1 = sm;                 // [32][32]  (m-major, k contiguous)
    float* sW2 = sW1 + 1024;         // [64][32]
    float* sW3 = sW2 + 2048;         // [96][64]
    float* sB  = sW3 + 6144;         // b1(32) b2(64) b3(96)
    float* h1s = sB + 192;           // [128][36]  pad-36 rows -> conflict-free
    float* h2s = h1s + 128 * 36;     // [128][68]

    const int tid = threadIdx.x;
    #pragma unroll 1
    for (int i = tid; i < 1024; i += 128) sW1[i] = W1[i];
    #pragma unroll 1
    for (int i = tid; i < 2048; i += 128) sW2[i] = W2[i];
    #pragma unroll 1
    for (int i = tid; i < 6144; i += 128) sW3[i] = W3[i];
    if (tid < 32)  sB[tid]      = b1[tid];
    if (tid < 64)  sB[32 + tid] = b2[tid];
    if (tid < 96)  sB[96 + tid] = b3[tid];
    __syncthreads();

    const int e = blockIdx.x * 128 + tid;
    if (e >= E) return;

    float* my1 = h1s + tid * 36;
    float* my2 = h2s + tid * 68;

    // edge_attr row -> registers
    float4 xv[8];
    const float4* ap = (const float4*)(edge_attr + (size_t)e * 32);
    #pragma unroll
    for (int i = 0; i < 8; i++) xv[i] = ap[i];

    // ---- layer 1: 32 -> 32 ----
    #pragma unroll 1
    for (int mg = 0; mg < 8; mg++) {
        const int m = mg * 4;
        const float4* w0 = (const float4*)(sW1 + (m + 0) * 32);
        const float4* w1 = (const float4*)(sW1 + (m + 1) * 32);
        const float4* w2 = (const float4*)(sW1 + (m + 2) * 32);
        const float4* w3 = (const float4*)(sW1 + (m + 3) * 32);
        float4 a0 = make_float4(0.f,0.f,0.f,0.f), a1 = a0, a2 = a0, a3 = a0;
        #pragma unroll
        for (int k = 0; k < 8; k++) {
            const float4 x = xv[k];
            fma4(a0, x, w0[k]); fma4(a1, x, w1[k]);
            fma4(a2, x, w2[k]); fma4(a3, x, w3[k]);
        }
        const float4 bb = *(const float4*)(sB + m);
        my1[m + 0] = silu_f(hsum4(a0) + bb.x);
        my1[m + 1] = silu_f(hsum4(a1) + bb.y);
        my1[m + 2] = silu_f(hsum4(a2) + bb.z);
        my1[m + 3] = silu_f(hsum4(a3) + bb.w);
    }

    // ---- layer 2: 32 -> 64 ----
    #pragma unroll 1
    for (int mg = 0; mg < 16; mg++) {
        const int m = mg * 4;
        const float4* w0 = (const float4*)(sW2 + (m + 0) * 32);
        const float4* w1 = (const float4*)(sW2 + (m + 1) * 32);
        const float4* w2 = (const float4*)(sW2 + (m + 2) * 32);
        const float4* w3 = (const float4*)(sW2 + (m + 3) * 32);
        const float4* xi = (const float4*)my1;
        float4 a0 = make_float4(0.f,0.f,0.f,0.f), a1 = a0, a2 = a0, a3 = a0;
        #pragma unroll
        for (int k = 0; k < 8; k++) {
            const float4 x = xi[k];
            fma4(a0, x, w0[k]); fma4(a1, x, w1[k]);
            fma4(a2, x, w2[k]); fma4(a3, x, w3[k]);
        }
        const float4 bb = *(const float4*)(sB + 32 + m);
        my2[m + 0] = silu_f(hsum4(a0) + bb.x);
        my2[m + 1] = silu_f(hsum4(a1) + bb.y);
        my2[m + 2] = silu_f(hsum4(a2) + bb.z);
        my2[m + 3] = silu_f(hsum4(a3) + bb.w);
    }

    // ---- layer 3: 64 -> 96, cutoff scale, vector-atomic accumulate ----
    const float wgt = edge_weight[e];
    const float cc  = (wgt < 5.0f)
                    ? (0.5f * (cosf(wgt * 0.62831853071795865f) + 1.0f))
                    : 0.0f;
    const int dst = edge_index[E + e];   // edge_index row 1
    float* ag = agg + (size_t)dst * 96;

    #pragma unroll 1
    for (int mg = 0; mg < 24; mg++) {
        const int m = mg * 4;
        const float4* w0 = (const float4*)(sW3 + (m + 0) * 64);
        const float4* w1 = (const float4*)(sW3 + (m + 1) * 64);
        const float4* w2 = (const float4*)(sW3 + (m + 2) * 64);
        const float4* w3 = (const float4*)(sW3 + (m + 3) * 64);
        const float4* xi = (const float4*)my2;
        float4 a0 = make_float4(0.f,0.f,0.f,0.f), a1 = a0, a2 = a0, a3 = a0;
        #pragma unroll
        for (int k = 0; k < 16; k++) {
            const float4 x = xi[k];
            fma4(a0, x, w0[k]); fma4(a1, x, w1[k]);
            fma4(a2, x, w2[k]); fma4(a3, x, w3[k]);
        }
        const float4 bb = *(const float4*)(sB + 96 + m);
        float4 r;
        r.x = silu_f(hsum4(a0) + bb.x) * cc;
        r.y = silu_f(hsum4(a1) + bb.y) * cc;
        r.z = silu_f(hsum4(a2) + bb.z) * cc;
        r.w = silu_f(hsum4(a3) + bb.w) * cc;
        atomicAdd((float4*)(ag + m), r);
    }
}

// --------------------------------------------------------------- node side
// warp per node, lane = unit. Components held per-lane, unit-mixing linears
// go through shared comps (broadcast reads) and shared Wt (stride-36 pad).
__device__ __forceinline__ void mix9(const float* __restrict__ wI,
                                     const float* __restrict__ wA,
                                     const float* __restrict__ wS,
                                     const float* __restrict__ cb,   // &cs[warp][0][0]
                                     float o[9])
{
    #pragma unroll
    for (int i = 0; i < 9; i++) o[i] = 0.f;
    #pragma unroll
    for (int k = 0; k < 8; k++) {
        const float4 vi = *(const float4*)(wI + 4 * k);
        const float4 va = *(const float4*)(wA + 4 * k);
        const float4 vs = *(const float4*)(wS + 4 * k);
        float4 c;
        c = *(const float4*)(cb + 0 * 32 + 4 * k);
        o[0] += vi.x*c.x + vi.y*c.y + vi.z*c.z + vi.w*c.w;
        c = *(const float4*)(cb + 1 * 32 + 4 * k);
        o[1] += va.x*c.x + va.y*c.y + va.z*c.z + va.w*c.w;
        c = *(const float4*)(cb + 2 * 32 + 4 * k);
        o[2] += va.x*c.x + va.y*c.y + va.z*c.z + va.w*c.w;
        c = *(const float4*)(cb + 3 * 32 + 4 * k);
        o[3] += va.x*c.x + va.y*c.y + va.z*c.z + va.w*c.w;
        c = *(const float4*)(cb + 4 * 32 + 4 * k);
        o[4] += vs.x*c.x + vs.y*c.y + vs.z*c.z + vs.w*c.w;
        c = *(const float4*)(cb + 5 * 32 + 4 * k);
        o[5] += vs.x*c.x + vs.y*c.y + vs.z*c.z + vs.w*c.w;
        c = *(const float4*)(cb + 6 * 32 + 4 * k);
        o[6] += vs.x*c.x + vs.y*c.y + vs.z*c.z + vs.w*c.w;
        c = *(const float4*)(cb + 7 * 32 + 4 * k);
        o[7] += vs.x*c.x + vs.y*c.y + vs.z*c.z + vs.w*c.w;
        c = *(const float4*)(cb + 8 * 32 + 4 * k);
        o[8] += vs.x*c.x + vs.y*c.y + vs.z*c.z + vs.w*c.w;
    }
}

__global__ __launch_bounds__(512) void node_kernel(
    const float* __restrict__ X,
    const float* __restrict__ Wt,
    const float* __restrict__ agg,
    float* __restrict__ out, int N)
{
    __shared__ __align__(16) float sWt[6 * 32 * 36];   // [t][m][k], k row padded to 36
    __shared__ __align__(16) float cs[16][9][32];      // per-warp component staging

    const int tid = threadIdx.x;
    #pragma unroll 1
    for (int i = tid; i < 6144; i += 512) {
        const int t = i >> 10, m = (i >> 5) & 31, k = i & 31;
        sWt[(t * 32 + m) * 36 + k] = Wt[i];
    }
    __syncthreads();

    const int warp = tid >> 5, lane = tid & 31;
    const int n = blockIdx.x * 16 + warp;
    if (n >= N) return;

    // load X[n,:,:,lane] (row-major i*3+j)
    const float* xp = X + (size_t)n * 288 + lane;
    float x[9];
    #pragma unroll
    for (int i = 0; i < 9; i++) x[i] = xp[i * 32];

    float nrm = 1.0f;
    #pragma unroll
    for (int i = 0; i < 9; i++) nrm += x[i] * x[i];
    const float inv = 1.0f / nrm;
    float xn[9];
    #pragma unroll
    for (int i = 0; i < 9; i++) xn[i] = x[i] * inv;

    // decompose Xn -> 9 independent comps {i0, a01,a02,a12, s00,s11,s01,s02,s12}
    const float tr3 = (xn[0] + xn[4] + xn[8]) * (1.0f / 3.0f);
    float c1[9];
    c1[0] = tr3;
    c1[1] = 0.5f * (xn[1] - xn[3]);
    c1[2] = 0.5f * (xn[2] - xn[6]);
    c1[3] = 0.5f * (xn[5] - xn[7]);
    c1[4] = xn[0] - tr3;
    c1[5] = xn[4] - tr3;
    c1[6] = 0.5f * (xn[1] + xn[3]);
    c1[7] = 0.5f * (xn[2] + xn[6]);
    c1[8] = 0.5f * (xn[5] + xn[7]);

    #pragma unroll
    for (int i = 0; i < 9; i++) cs[warp][i][lane] = c1[i];
    __syncwarp();

    float o[9];   // post-linear comps (Iy, Ay*, Sy*)
    mix9(sWt + (0 * 32 + lane) * 36,
         sWt + (1 * 32 + lane) * 36,
         sWt + (2 * 32 + lane) * 36,
         &cs[warp][0][0], o);

    // per-(node,unit) aggregated edge weights
    const float* ag = agg + (size_t)n * 96 + lane * 3;
    const float aI = ag[0], aA = ag[1], aS = ag[2];

    // full 3x3 Y and msg G per unit
    float Y[9], G[9];
    Y[0] = o[0] + o[4];  Y[1] = o[6] + o[1];  Y[2] = o[7] + o[2];
    Y[3] = o[6] - o[1];  Y[4] = o[0] + o[5];  Y[5] = o[8] + o[3];
    Y[6] = o[7] - o[2];  Y[7] = o[8] - o[3];  Y[8] = o[0] - o[4] - o[5];

    const float mI = o[0] * aI;
    const float mA1 = o[1] * aA, mA2 = o[2] * aA, mA3 = o[3] * aA;
    const float mS4 = o[4] * aS, mS5 = o[5] * aS;
    const float mS6 = o[6] * aS, mS7 = o[7] * aS, mS8 = o[8] * aS;
    G[0] = mI + mS4;   G[1] = mS6 + mA1;  G[2] = mS7 + mA2;
    G[3] = mS6 - mA1;  G[4] = mI + mS5;   G[5] = mS8 + mA3;
    G[6] = mS7 - mA2;  G[7] = mS8 - mA3;  G[8] = mI - mS4 - mS5;

    // M = Y*G + G*Y (3x3 per unit)
    float M[9];
    #pragma unroll
    for (int i = 0; i < 3; i++) {
        #pragma unroll
        for (int l = 0; l < 3; l++) {
            float s = 0.f;
            #pragma unroll
            for (int j = 0; j < 3; j++)
                s += Y[i*3+j] * G[j*3+l] + G[i*3+j] * Y[j*3+l];
            M[i*3+l] = s;
        }
    }

    float nrm2 = 1.0f;
    #pragma unroll
    for (int i = 0; i < 9; i++) nrm2 += M[i] * M[i];
    const float inv2 = 1.0f / nrm2;

    const float tm = (M[0] + M[4] + M[8]) * (1.0f / 3.0f);
    float c2[9];
    c2[0] = tm;
    c2[1] = 0.5f * (M[1] - M[3]);
    c2[2] = 0.5f * (M[2] - M[6]);
    c2[3] = 0.5f * (M[5] - M[7]);
    c2[4] = M[0] - tm;
    c2[5] = M[4] - tm;
    c2[6] = 0.5f * (M[1] + M[3]);
    c2[7] = 0.5f * (M[2] + M[6]);
    c2[8] = 0.5f * (M[5] + M[7]);
    #pragma unroll
    for (int i = 0; i < 9; i++) c2[i] *= inv2;

    __syncwarp();
    #pragma unroll
    for (int i = 0; i < 9; i++) cs[warp][i][lane] = c2[i];
    __syncwarp();

    float d[9];
    mix9(sWt + (3 * 32 + lane) * 36,
         sWt + (4 * 32 + lane) * 36,
         sWt + (5 * 32 + lane) * 36,
         &cs[warp][0][0], d);

    // dX full 3x3
    float D[9];
    D[0] = d[0] + d[4];  D[1] = d[6] + d[1];  D[2] = d[7] + d[2];
    D[3] = d[6] - d[1];  D[4] = d[0] + d[5];  D[5] = d[8] + d[3];
    D[6] = d[7] - d[2];  D[7] = d[8] - d[3];  D[8] = d[0] - d[4] - d[5];

    // out = Xn + dX + dX@dX
    float* op = out + (size_t)n * 288 + lane;
    #pragma unroll
    for (int i = 0; i < 3; i++) {
        #pragma unroll
        for (int l = 0; l < 3; l++) {
            float s = xn[i*3+l] + D[i*3+l];
            #pragma unroll
            for (int j = 0; j < 3; j++)
                s += D[i*3+j] * D[j*3+l];
            op[(i*3+l) * 32] = s;
        }
    }
}

// ------------------------------------------------------------------- launch
extern "C" void kernel_launch(void* const* d_in, const int* in_sizes, int n_in,
                              void* d_out, int out_size)
{
    const float* X  = (const float*)d_in[0];
    const int*   ei = (const int*)  d_in[1];
    const float* ew = (const float*)d_in[2];
    const float* ea = (const float*)d_in[3];
    const float* W1 = (const float*)d_in[4];
    const float* b1 = (const float*)d_in[5];
    const float* W2 = (const float*)d_in[6];
    const float* b2 = (const float*)d_in[7];
    const float* W3 = (const float*)d_in[8];
    const float* b3 = (const float*)d_in[9];
    const float* Wt = (const float*)d_in[10];
    float* out = (float*)d_out;

    const int N = in_sizes[0] / 288;   // X: (N,3,3,32)
    const int E = in_sizes[2];         // edge_weight: (E,)

    float* agg = nullptr;
    cudaGetSymbolAddress((void**)&agg, g_agg);

    // 1) zero per-node accumulator
    const int n4 = N * 24;             // N*96/4 float4s
    zero_kernel<<<(n4 + 255) / 256, 256>>>((float4*)agg, n4);

    // 2) edge MLP + atomic segment accumulation
    const int edge_smem = (1024 + 2048 + 6144 + 192 + 128 * 36 + 128 * 68) * 4; // 90880 B
    cudaFuncSetAttribute(edge_kernel, cudaFuncAttributeMaxDynamicSharedMemorySize, edge_smem);
    edge_kernel<<<(E + 127) / 128, 128, edge_smem>>>(
        ea, ew, ei, W1, b1, W2, b2, W3, b3, agg, E);

    // 3) node-local tensor update
    node_kernel<<<(N + 15) / 16, 512>>>(X, Wt, agg, out, N);
}